// round 2
// baseline (speedup 1.0000x reference)
#include <cuda_runtime.h>

#define EPS   1.1920928955078125e-07f
#define SCALE 0.17677669529663687f   // 1/sqrt(32)

// scratch (static __device__ — no allocations allowed); 16B-aligned for float4
__device__ __align__(16) float g_wct[9 * 128 * 128];   // conv weights, [dydx][ci][oc]
__device__ __align__(16) float g_wqt[128 * 128];       // qproj_w^T * normq_w, [c][o]
__device__ __align__(16) float g_wkt[128 * 128];       // kproj_w^T * normk_w, [c][o]
__device__ __align__(16) float g_qn[128 * 128 * 128];  // projected q, [pixel][c]
__device__ __align__(16) float g_kd[32 * 32 * 128];    // projected k (downsampled), [pixel][c]
__device__ __align__(16) float g_vd[32 * 32 * 128];    // v transposed, [pixel][c]

// ---------------------------------------------------------------------------
// Kernel 0: weight prep (transpose conv weights; fold RMSNorm gains into projs)
// ---------------------------------------------------------------------------
__global__ void prep_kernel(const float* __restrict__ conv_w,
                            const float* __restrict__ normq,
                            const float* __restrict__ normk,
                            const float* __restrict__ qw,
                            const float* __restrict__ kw) {
    int idx = blockIdx.x * 256 + threadIdx.x;
    if (idx < 9 * 128 * 128) {
        int oc = idx & 127;
        int t = idx >> 7;
        int ci = t & 127;
        int dydx = t >> 7;
        g_wct[idx] = conv_w[(oc * 128 + ci) * 9 + dydx];
    }
    if (idx < 128 * 128) {
        int o = idx & 127;
        int c = idx >> 7;
        g_wqt[idx] = qw[o * 128 + c] * normq[c];
        g_wkt[idx] = kw[o * 128 + c] * normk[c];
    }
}

// ---------------------------------------------------------------------------
// Kernel 1: fused conv3x3 (SAME, no bias) + RMSNorm + qproj (1x1, bias)
// block = 8x8 output pixels, all 128 out channels. 256 thr, thread tile 8oc x 4px.
// smem: patch[100][129] | wbuf[64][128] | rstd[64];  cout reuses patch region.
// ---------------------------------------------------------------------------
__global__ __launch_bounds__(256, 2)
void convq_kernel(const float* __restrict__ qin, const float* __restrict__ qb) {
    extern __shared__ float sm[];
    float* patch = sm;                   // 100*129 = 12900
    float* wbuf  = sm + 12900;           // 64*128  = 8192  (12900*4 % 16 == 0)
    float* rstd  = sm + 12900 + 8192;    // 64
    float* coutb = sm;                   // reuse: 64*129 = 8256 <= 12900

    const int tid = threadIdx.x;
    const int tx = tid & 15;             // oc block: oc = tx*8 .. tx*8+7
    const int ty = tid >> 4;             // pixel group: p = ty*4+i
    const int gx0 = blockIdx.x * 8 - 1;
    const int gy0 = blockIdx.y * 8 - 1;

    // load 10x10x128 input patch (zero-padded), layout [pix][ci], stride 129
    for (int idx = tid; idx < 12800; idx += 256) {
        int ci = idx / 100;
        int pix = idx - ci * 100;
        int yy = pix / 10;
        int xx = pix - yy * 10;
        int gy = gy0 + yy, gx = gx0 + xx;
        float v = 0.f;
        if ((unsigned)gy < 128u && (unsigned)gx < 128u)
            v = qin[ci * 16384 + gy * 128 + gx];
        patch[pix * 129 + ci] = v;
    }

    int pbase[4];
#pragma unroll
    for (int i = 0; i < 4; i++) {
        int p = ty * 4 + i;
        pbase[i] = (p >> 3) * 10 + (p & 7);
    }

    float acc[4][8];
#pragma unroll
    for (int i = 0; i < 4; i++)
#pragma unroll
        for (int o = 0; o < 8; o++) acc[i][o] = 0.f;

    for (int dydx = 0; dydx < 9; dydx++) {
        const int dy = dydx / 3, dx = dydx - dy * 3;
        int pofs[4];
#pragma unroll
        for (int i = 0; i < 4; i++) pofs[i] = (pbase[i] + dy * 10 + dx) * 129;
        for (int ch = 0; ch < 2; ch++) {
            __syncthreads();
            const float4* src = (const float4*)(g_wct + (dydx * 128 + ch * 64) * 128);
            float4* dst = (float4*)wbuf;
            for (int j = tid; j < 2048; j += 256) dst[j] = src[j];
            __syncthreads();
#pragma unroll 2
            for (int cl = 0; cl < 64; cl++) {
                const int ci = ch * 64 + cl;
                float in0 = patch[pofs[0] + ci];
                float in1 = patch[pofs[1] + ci];
                float in2 = patch[pofs[2] + ci];
                float in3 = patch[pofs[3] + ci];
                const float* wrow = wbuf + cl * 128 + tx * 8;
                float4 w0 = *(const float4*)wrow;
                float4 w1 = *(const float4*)(wrow + 4);
                float w[8] = {w0.x, w0.y, w0.z, w0.w, w1.x, w1.y, w1.z, w1.w};
#pragma unroll
                for (int o = 0; o < 8; o++) {
                    acc[0][o] += in0 * w[o];
                    acc[1][o] += in1 * w[o];
                    acc[2][o] += in2 * w[o];
                    acc[3][o] += in3 * w[o];
                }
            }
        }
    }
    __syncthreads();
    // stage conv result [px][oc] (stride 129), overwrites patch
#pragma unroll
    for (int i = 0; i < 4; i++) {
        int p = ty * 4 + i;
#pragma unroll
        for (int o = 0; o < 8; o++) coutb[p * 129 + tx * 8 + o] = acc[i][o];
    }
    __syncthreads();
    if (tid < 64) {
        float ss = 0.f;
        const float* row = coutb + tid * 129;
        for (int c = 0; c < 128; c++) { float v = row[c]; ss += v * v; }
        rstd[tid] = rsqrtf(ss * (1.0f / 128.0f) + EPS);
    }

    // qproj GEMM: out[o][p] = sum_c wqt[c][o] * cout[p][c]
    float pacc[4][8];
#pragma unroll
    for (int i = 0; i < 4; i++)
#pragma unroll
        for (int o = 0; o < 8; o++) pacc[i][o] = 0.f;

    int rofs[4];
#pragma unroll
    for (int i = 0; i < 4; i++) rofs[i] = (ty * 4 + i) * 129;

    for (int ch = 0; ch < 2; ch++) {
        __syncthreads();
        const float4* src = (const float4*)(g_wqt + ch * 64 * 128);
        float4* dst = (float4*)wbuf;
        for (int j = tid; j < 2048; j += 256) dst[j] = src[j];
        __syncthreads();
#pragma unroll 2
        for (int cl = 0; cl < 64; cl++) {
            const int c = ch * 64 + cl;
            float in0 = coutb[rofs[0] + c];
            float in1 = coutb[rofs[1] + c];
            float in2 = coutb[rofs[2] + c];
            float in3 = coutb[rofs[3] + c];
            const float* wrow = wbuf + cl * 128 + tx * 8;
            float4 w0 = *(const float4*)wrow;
            float4 w1 = *(const float4*)(wrow + 4);
            float w[8] = {w0.x, w0.y, w0.z, w0.w, w1.x, w1.y, w1.z, w1.w};
#pragma unroll
            for (int o = 0; o < 8; o++) {
                pacc[0][o] += in0 * w[o];
                pacc[1][o] += in1 * w[o];
                pacc[2][o] += in2 * w[o];
                pacc[3][o] += in3 * w[o];
            }
        }
    }

    float bias[8];
#pragma unroll
    for (int o = 0; o < 8; o++) bias[o] = qb[tx * 8 + o];
#pragma unroll
    for (int i = 0; i < 4; i++) {
        int p = ty * 4 + i;
        int gy = blockIdx.y * 8 + (p >> 3);
        int gx = blockIdx.x * 8 + (p & 7);
        float r = rstd[p];
        float* outp = g_qn + (gy * 128 + gx) * 128 + tx * 8;
        float4 o0, o1;
        o0.x = pacc[i][0] * r + bias[0];
        o0.y = pacc[i][1] * r + bias[1];
        o0.z = pacc[i][2] * r + bias[2];
        o0.w = pacc[i][3] * r + bias[3];
        o1.x = pacc[i][4] * r + bias[4];
        o1.y = pacc[i][5] * r + bias[5];
        o1.z = pacc[i][6] * r + bias[6];
        o1.w = pacc[i][7] * r + bias[7];
        *(float4*)outp = o0;
        *(float4*)(outp + 4) = o1;
    }
}

// ---------------------------------------------------------------------------
// Kernel 2: k path (RMSNorm + kproj) on 32x32 grid, plus v transpose.
// 64 blocks x 16 pixels. 256 thr, thread tile 8oc x 1px.
// ---------------------------------------------------------------------------
__global__ __launch_bounds__(256)
void kprep_kernel(const float* __restrict__ kin, const float* __restrict__ vin,
                  const float* __restrict__ kb) {
    extern __shared__ float sm2[];
    float* ksh  = sm2;                 // 16*129 = 2064  (2064*4 % 16 == 0 for wbuf)
    float* wbuf = sm2 + 2064;          // 8192
    float* rstd = sm2 + 2064 + 8192;   // 16
    const int tid = threadIdx.x;
    const int tx = tid & 15;
    const int ty = tid >> 4;
    const int pbase = blockIdx.x * 16;

    for (int idx = tid; idx < 2048; idx += 256) {
        int c = idx >> 4, pp = idx & 15;
        ksh[pp * 129 + c] = kin[c * 1024 + pbase + pp];
    }
    __syncthreads();
    if (tid < 16) {
        float ss = 0.f;
        const float* row = ksh + tid * 129;
        for (int c = 0; c < 128; c++) { float v = row[c]; ss += v * v; }
        rstd[tid] = rsqrtf(ss * (1.0f / 128.0f) + EPS);
    }
    float pacc[8];
#pragma unroll
    for (int o = 0; o < 8; o++) pacc[o] = 0.f;
    const int rofs = ty * 129;
    for (int ch = 0; ch < 2; ch++) {
        __syncthreads();
        const float4* src = (const float4*)(g_wkt + ch * 64 * 128);
        float4* dst = (float4*)wbuf;
        for (int j = tid; j < 2048; j += 256) dst[j] = src[j];
        __syncthreads();
#pragma unroll 2
        for (int cl = 0; cl < 64; cl++) {
            float in0 = ksh[rofs + ch * 64 + cl];
            const float* wrow = wbuf + cl * 128 + tx * 8;
            float4 w0 = *(const float4*)wrow;
            float4 w1 = *(const float4*)(wrow + 4);
            pacc[0] += in0 * w0.x; pacc[1] += in0 * w0.y;
            pacc[2] += in0 * w0.z; pacc[3] += in0 * w0.w;
            pacc[4] += in0 * w1.x; pacc[5] += in0 * w1.y;
            pacc[6] += in0 * w1.z; pacc[7] += in0 * w1.w;
        }
    }
    {
        float r = rstd[ty];
        float* outp = g_kd + (pbase + ty) * 128 + tx * 8;
        float4 o0, o1;
        o0.x = pacc[0] * r + kb[tx * 8 + 0];
        o0.y = pacc[1] * r + kb[tx * 8 + 1];
        o0.z = pacc[2] * r + kb[tx * 8 + 2];
        o0.w = pacc[3] * r + kb[tx * 8 + 3];
        o1.x = pacc[4] * r + kb[tx * 8 + 4];
        o1.y = pacc[5] * r + kb[tx * 8 + 5];
        o1.z = pacc[6] * r + kb[tx * 8 + 6];
        o1.w = pacc[7] * r + kb[tx * 8 + 7];
        *(float4*)outp = o0;
        *(float4*)(outp + 4) = o1;
    }
    // v transpose (channel-major -> pixel-major) via smem
    __syncthreads();
    for (int idx = tid; idx < 2048; idx += 256) {
        int c = idx >> 4, pp = idx & 15;
        ksh[pp * 129 + c] = vin[c * 1024 + pbase + pp];
    }
    __syncthreads();
    for (int idx = tid; idx < 2048; idx += 256) {
        int pp = idx >> 7, c = idx & 127;
        g_vd[(pbase + pp) * 128 + c] = ksh[pp * 129 + c];
    }
}

// ---------------------------------------------------------------------------
// Kernel 3: NATTEN attention. One block per 4x4 query block (all 16 queries
// share the same 7x7 downsampled K/V window). 1024 blocks x 256 threads.
// All float4-accessed smem regions are 16B-aligned (offsets multiple of 4 floats).
// ---------------------------------------------------------------------------
__global__ __launch_bounds__(256, 3)
void attn_kernel(float* __restrict__ out) {
    extern __shared__ float sm3[];
    float* ksh = sm3;                        // 49*129 = 6321, padded to 6336
    float* vsh = sm3 + 6336;                 // 49*128 = 6272  (16B aligned)
    float* qsh = sm3 + 6336 + 6272;          // 12608: 16*128 = 2048 (16B aligned)
    float* lg  = sm3 + 6336 + 6272 + 2048;   // 14656: 16*197 = 3152
    float* am  = lg + 3152;                  // 17808: 16*49  = 784 -> end 18592
    float* osh = lg;                         // reuse lg region: 128*17 = 2176 (scalar)

    const int tid = threadIdx.x;
    const int bx = blockIdx.x, by = blockIdx.y;
    int ks_h = min(max(by - 3, 0), 25);
    int ks_w = min(max(bx - 3, 0), 25);

    // stage K, V windows (49 pixels x 128 ch)
    for (int idx = tid; idx < 6272; idx += 256) {
        int kk = idx >> 7, c = idx & 127;
        int m = kk / 7, n = kk - m * 7;
        int gp = (ks_h + m) * 32 + (ks_w + n);
        ksh[kk * 129 + c] = g_kd[gp * 128 + c];
        vsh[kk * 128 + c] = g_vd[gp * 128 + c];
    }
    // stage Q (16 queries x 128 ch)
    for (int idx = tid; idx < 2048; idx += 256) {
        int qq = idx >> 7, c = idx & 127;
        int gi = by * 4 + (qq >> 2), gj = bx * 4 + (qq & 3);
        qsh[idx] = g_qn[(gi * 128 + gj) * 128 + c];
    }
    __syncthreads();

    // phase 1: logits, 2 queries per job to halve shared loads
    for (int job = tid; job < 1568; job += 256) {
        int qp = job / 196;
        int hkk = job - qp * 196;
        int h = hkk / 49;
        int kk = hkk - h * 49;
        const float* kp = ksh + kk * 129 + h * 32;
        const float* q0 = qsh + (qp * 2) * 128 + h * 32;
        const float* q1 = q0 + 128;
        float a0 = 0.f, a1 = 0.f;
#pragma unroll
        for (int c = 0; c < 32; c++) {
            float kv = kp[c];
            a0 += q0[c] * kv;
            a1 += q1[c] * kv;
        }
        lg[(qp * 2) * 197 + hkk] = a0 * SCALE;
        lg[(qp * 2 + 1) * 197 + hkk] = a1 * SCALE;
    }
    __syncthreads();

    // phase 2: per-(q,h) softmax, pre-scaled by 1/4 for head-mean
    if (tid < 64) {
        int q = tid >> 2, h = tid & 3;
        float* base = lg + q * 197 + h * 49;
        float mx = base[0];
        for (int k = 1; k < 49; k++) mx = fmaxf(mx, base[k]);
        float s = 0.f;
        for (int k = 0; k < 49; k++) { float e = __expf(base[k] - mx); base[k] = e; s += e; }
        float inv = 0.25f / s;
        for (int k = 0; k < 49; k++) base[k] *= inv;
    }
    __syncthreads();
    // phase 2b: head-mean attention weights
    for (int job = tid; job < 784; job += 256) {
        int q = job / 49, kk = job - q * 49;
        const float* b = lg + q * 197 + kk;
        am[job] = b[0] + b[49] + b[98] + b[147];
    }
    __syncthreads();

    // phase 3: out[q][c] = sum_kk am[q][kk] * V[kk][c]; thread = (q, 8 channels)
    {
        const int q = tid >> 4;
        const int cb = (tid & 15) * 8;
        float racc[8];
#pragma unroll
        for (int j = 0; j < 8; j++) racc[j] = 0.f;
        const float* amq = am + q * 49;
        for (int kk = 0; kk < 49; kk++) {
            float a = amq[kk];
            const float4 v0 = *(const float4*)(vsh + kk * 128 + cb);
            const float4 v1 = *(const float4*)(vsh + kk * 128 + cb + 4);
            racc[0] += a * v0.x; racc[1] += a * v0.y;
            racc[2] += a * v0.z; racc[3] += a * v0.w;
            racc[4] += a * v1.x; racc[5] += a * v1.y;
            racc[6] += a * v1.z; racc[7] += a * v1.w;
        }
        // osh overlaps lg which is no longer read (am is a separate buffer)
#pragma unroll
        for (int j = 0; j < 8; j++) osh[(cb + j) * 17 + q] = racc[j];
    }
    __syncthreads();
    // final store: [c][4x4 pixel tile] as float4 rows
    for (int job = tid; job < 512; job += 256) {
        int c = job >> 2, i = job & 3;
        const float* b = osh + c * 17 + i * 4;
        float4 v;
        v.x = b[0]; v.y = b[1]; v.z = b[2]; v.w = b[3];
        *(float4*)(out + c * 16384 + (by * 4 + i) * 128 + bx * 4) = v;
    }
}

// ---------------------------------------------------------------------------
extern "C" void kernel_launch(void* const* d_in, const int* in_sizes, int n_in,
                              void* d_out, int out_size) {
    const float* q  = (const float*)d_in[0];
    const float* k  = (const float*)d_in[1];
    const float* v  = (const float*)d_in[2];
    const float* cw = (const float*)d_in[3];
    const float* nq = (const float*)d_in[4];
    const float* nk = (const float*)d_in[5];
    const float* qw = (const float*)d_in[6];
    const float* qb = (const float*)d_in[7];
    const float* kw = (const float*)d_in[8];
    const float* kb = (const float*)d_in[9];
    float* out = (float*)d_out;

    cudaFuncSetAttribute(convq_kernel, cudaFuncAttributeMaxDynamicSharedMemorySize, 84624);
    cudaFuncSetAttribute(attn_kernel, cudaFuncAttributeMaxDynamicSharedMemorySize, 74368);

    prep_kernel<<<576, 256>>>(cw, nq, nk, qw, kw);
    convq_kernel<<<dim3(16, 16), 256, 84624>>>(q, qb);
    kprep_kernel<<<64, 256, 41088>>>(k, v, kb);
    attn_kernel<<<dim3(32, 32), 256, 74368>>>(out);
}

// round 3
// speedup vs baseline: 1.0017x; 1.0017x over previous
#include <cuda_runtime.h>

#define EPS   1.1920928955078125e-07f
#define SCALE 0.17677669529663687f   // 1/sqrt(32)

// scratch (static __device__ — no allocations allowed); 16B-aligned for float4
__device__ __align__(16) float g_wct[9 * 128 * 128];   // conv weights, [dydx][ci][oc]
__device__ __align__(16) float g_wqt[128 * 128];       // qproj_w^T * normq_w, [c][o]
__device__ __align__(16) float g_wkt[128 * 128];       // kproj_w^T * normk_w, [c][o]
__device__ __align__(16) float g_qn[128 * 128 * 128];  // projected q, [pixel][c]
__device__ __align__(16) float g_kd[32 * 32 * 128];    // projected k (downsampled), [pixel][c]
__device__ __align__(16) float g_vd[32 * 32 * 128];    // v transposed, [pixel][c]

// ---------------------------------------------------------------------------
// Kernel 0: weight prep (transpose conv weights; fold RMSNorm gains into projs)
// ---------------------------------------------------------------------------
__global__ void prep_kernel(const float* __restrict__ conv_w,
                            const float* __restrict__ normq,
                            const float* __restrict__ normk,
                            const float* __restrict__ qw,
                            const float* __restrict__ kw) {
    int idx = blockIdx.x * 256 + threadIdx.x;
    if (idx < 9 * 128 * 128) {
        int oc = idx & 127;
        int t = idx >> 7;
        int ci = t & 127;
        int dydx = t >> 7;
        g_wct[idx] = conv_w[(oc * 128 + ci) * 9 + dydx];
    }
    if (idx < 128 * 128) {
        int o = idx & 127;
        int c = idx >> 7;
        g_wqt[idx] = qw[o * 128 + c] * normq[c];
        g_wkt[idx] = kw[o * 128 + c] * normk[c];
    }
}

// ---------------------------------------------------------------------------
// Kernel 1: fused conv3x3 (SAME, no bias) + RMSNorm + qproj (1x1, bias)
// block = 8x8 output pixels, all 128 out channels. 256 thr, thread tile 8oc x 4px.
// smem: patch[100][129] | wbuf[64][128] | rstd[64];  cout reuses patch region.
// ---------------------------------------------------------------------------
__global__ __launch_bounds__(256, 2)
void convq_kernel(const float* __restrict__ qin, const float* __restrict__ qb) {
    extern __shared__ float sm[];
    float* patch = sm;                   // 100*129 = 12900
    float* wbuf  = sm + 12900;           // 64*128  = 8192  (12900*4 % 16 == 0)
    float* rstd  = sm + 12900 + 8192;    // 64
    float* coutb = sm;                   // reuse: 64*129 = 8256 <= 12900

    const int tid = threadIdx.x;
    const int tx = tid & 15;             // oc block: oc = tx*8 .. tx*8+7
    const int ty = tid >> 4;             // pixel group: p = ty*4+i
    const int gx0 = blockIdx.x * 8 - 1;
    const int gy0 = blockIdx.y * 8 - 1;

    // load 10x10x128 input patch (zero-padded), layout [pix][ci], stride 129
    for (int idx = tid; idx < 12800; idx += 256) {
        int ci = idx / 100;
        int pix = idx - ci * 100;
        int yy = pix / 10;
        int xx = pix - yy * 10;
        int gy = gy0 + yy, gx = gx0 + xx;
        float v = 0.f;
        if ((unsigned)gy < 128u && (unsigned)gx < 128u)
            v = qin[ci * 16384 + gy * 128 + gx];
        patch[pix * 129 + ci] = v;
    }

    int pbase[4];
#pragma unroll
    for (int i = 0; i < 4; i++) {
        int p = ty * 4 + i;
        pbase[i] = (p >> 3) * 10 + (p & 7);
    }

    float acc[4][8];
#pragma unroll
    for (int i = 0; i < 4; i++)
#pragma unroll
        for (int o = 0; o < 8; o++) acc[i][o] = 0.f;

    for (int dydx = 0; dydx < 9; dydx++) {
        const int dy = dydx / 3, dx = dydx - dy * 3;
        int pofs[4];
#pragma unroll
        for (int i = 0; i < 4; i++) pofs[i] = (pbase[i] + dy * 10 + dx) * 129;
        for (int ch = 0; ch < 2; ch++) {
            __syncthreads();
            const float4* src = (const float4*)(g_wct + (dydx * 128 + ch * 64) * 128);
            float4* dst = (float4*)wbuf;
            for (int j = tid; j < 2048; j += 256) dst[j] = src[j];
            __syncthreads();
#pragma unroll 2
            for (int cl = 0; cl < 64; cl++) {
                const int ci = ch * 64 + cl;
                float in0 = patch[pofs[0] + ci];
                float in1 = patch[pofs[1] + ci];
                float in2 = patch[pofs[2] + ci];
                float in3 = patch[pofs[3] + ci];
                const float* wrow = wbuf + cl * 128 + tx * 8;
                float4 w0 = *(const float4*)wrow;
                float4 w1 = *(const float4*)(wrow + 4);
                float w[8] = {w0.x, w0.y, w0.z, w0.w, w1.x, w1.y, w1.z, w1.w};
#pragma unroll
                for (int o = 0; o < 8; o++) {
                    acc[0][o] += in0 * w[o];
                    acc[1][o] += in1 * w[o];
                    acc[2][o] += in2 * w[o];
                    acc[3][o] += in3 * w[o];
                }
            }
        }
    }
    __syncthreads();
    // stage conv result [px][oc] (stride 129), overwrites patch
#pragma unroll
    for (int i = 0; i < 4; i++) {
        int p = ty * 4 + i;
#pragma unroll
        for (int o = 0; o < 8; o++) coutb[p * 129 + tx * 8 + o] = acc[i][o];
    }
    __syncthreads();
    if (tid < 64) {
        float ss = 0.f;
        const float* row = coutb + tid * 129;
        for (int c = 0; c < 128; c++) { float v = row[c]; ss += v * v; }
        rstd[tid] = rsqrtf(ss * (1.0f / 128.0f) + EPS);
    }

    // qproj GEMM: out[o][p] = sum_c wqt[c][o] * cout[p][c]
    float pacc[4][8];
#pragma unroll
    for (int i = 0; i < 4; i++)
#pragma unroll
        for (int o = 0; o < 8; o++) pacc[i][o] = 0.f;

    int rofs[4];
#pragma unroll
    for (int i = 0; i < 4; i++) rofs[i] = (ty * 4 + i) * 129;

    for (int ch = 0; ch < 2; ch++) {
        __syncthreads();
        const float4* src = (const float4*)(g_wqt + ch * 64 * 128);
        float4* dst = (float4*)wbuf;
        for (int j = tid; j < 2048; j += 256) dst[j] = src[j];
        __syncthreads();
#pragma unroll 2
        for (int cl = 0; cl < 64; cl++) {
            const int c = ch * 64 + cl;
            float in0 = coutb[rofs[0] + c];
            float in1 = coutb[rofs[1] + c];
            float in2 = coutb[rofs[2] + c];
            float in3 = coutb[rofs[3] + c];
            const float* wrow = wbuf + cl * 128 + tx * 8;
            float4 w0 = *(const float4*)wrow;
            float4 w1 = *(const float4*)(wrow + 4);
            float w[8] = {w0.x, w0.y, w0.z, w0.w, w1.x, w1.y, w1.z, w1.w};
#pragma unroll
            for (int o = 0; o < 8; o++) {
                pacc[0][o] += in0 * w[o];
                pacc[1][o] += in1 * w[o];
                pacc[2][o] += in2 * w[o];
                pacc[3][o] += in3 * w[o];
            }
        }
    }

    float bias[8];
#pragma unroll
    for (int o = 0; o < 8; o++) bias[o] = qb[tx * 8 + o];
#pragma unroll
    for (int i = 0; i < 4; i++) {
        int p = ty * 4 + i;
        int gy = blockIdx.y * 8 + (p >> 3);
        int gx = blockIdx.x * 8 + (p & 7);
        float r = rstd[p];
        float* outp = g_qn + (gy * 128 + gx) * 128 + tx * 8;
        float4 o0, o1;
        o0.x = pacc[i][0] * r + bias[0];
        o0.y = pacc[i][1] * r + bias[1];
        o0.z = pacc[i][2] * r + bias[2];
        o0.w = pacc[i][3] * r + bias[3];
        o1.x = pacc[i][4] * r + bias[4];
        o1.y = pacc[i][5] * r + bias[5];
        o1.z = pacc[i][6] * r + bias[6];
        o1.w = pacc[i][7] * r + bias[7];
        *(float4*)outp = o0;
        *(float4*)(outp + 4) = o1;
    }
}

// ---------------------------------------------------------------------------
// Kernel 2: k path (RMSNorm + kproj) on 32x32 grid, plus v transpose.
// 64 blocks x 16 pixels. 256 thr, thread tile 8oc x 1px.
// ---------------------------------------------------------------------------
__global__ __launch_bounds__(256)
void kprep_kernel(const float* __restrict__ kin, const float* __restrict__ vin,
                  const float* __restrict__ kb) {
    extern __shared__ float sm2[];
    float* ksh  = sm2;                 // 16*129 = 2064  (2064*4 % 16 == 0 for wbuf)
    float* wbuf = sm2 + 2064;          // 8192
    float* rstd = sm2 + 2064 + 8192;   // 16
    const int tid = threadIdx.x;
    const int tx = tid & 15;
    const int ty = tid >> 4;
    const int pbase = blockIdx.x * 16;

    for (int idx = tid; idx < 2048; idx += 256) {
        int c = idx >> 4, pp = idx & 15;
        ksh[pp * 129 + c] = kin[c * 1024 + pbase + pp];
    }
    __syncthreads();
    if (tid < 16) {
        float ss = 0.f;
        const float* row = ksh + tid * 129;
        for (int c = 0; c < 128; c++) { float v = row[c]; ss += v * v; }
        rstd[tid] = rsqrtf(ss * (1.0f / 128.0f) + EPS);
    }
    float pacc[8];
#pragma unroll
    for (int o = 0; o < 8; o++) pacc[o] = 0.f;
    const int rofs = ty * 129;
    for (int ch = 0; ch < 2; ch++) {
        __syncthreads();
        const float4* src = (const float4*)(g_wkt + ch * 64 * 128);
        float4* dst = (float4*)wbuf;
        for (int j = tid; j < 2048; j += 256) dst[j] = src[j];
        __syncthreads();
#pragma unroll 2
        for (int cl = 0; cl < 64; cl++) {
            float in0 = ksh[rofs + ch * 64 + cl];
            const float* wrow = wbuf + cl * 128 + tx * 8;
            float4 w0 = *(const float4*)wrow;
            float4 w1 = *(const float4*)(wrow + 4);
            pacc[0] += in0 * w0.x; pacc[1] += in0 * w0.y;
            pacc[2] += in0 * w0.z; pacc[3] += in0 * w0.w;
            pacc[4] += in0 * w1.x; pacc[5] += in0 * w1.y;
            pacc[6] += in0 * w1.z; pacc[7] += in0 * w1.w;
        }
    }
    {
        float r = rstd[ty];
        float* outp = g_kd + (pbase + ty) * 128 + tx * 8;
        float4 o0, o1;
        o0.x = pacc[0] * r + kb[tx * 8 + 0];
        o0.y = pacc[1] * r + kb[tx * 8 + 1];
        o0.z = pacc[2] * r + kb[tx * 8 + 2];
        o0.w = pacc[3] * r + kb[tx * 8 + 3];
        o1.x = pacc[4] * r + kb[tx * 8 + 4];
        o1.y = pacc[5] * r + kb[tx * 8 + 5];
        o1.z = pacc[6] * r + kb[tx * 8 + 6];
        o1.w = pacc[7] * r + kb[tx * 8 + 7];
        *(float4*)outp = o0;
        *(float4*)(outp + 4) = o1;
    }
    // v transpose (channel-major -> pixel-major) via smem
    __syncthreads();
    for (int idx = tid; idx < 2048; idx += 256) {
        int c = idx >> 4, pp = idx & 15;
        ksh[pp * 129 + c] = vin[c * 1024 + pbase + pp];
    }
    __syncthreads();
    for (int idx = tid; idx < 2048; idx += 256) {
        int pp = idx >> 7, c = idx & 127;
        g_vd[(pbase + pp) * 128 + c] = ksh[pp * 129 + c];
    }
}

// ---------------------------------------------------------------------------
// Kernel 3: NATTEN attention. One block per 4x4 query block (all 16 queries
// share the same 7x7 downsampled K/V window). 1024 blocks x 256 threads.
// All float4-accessed smem regions are 16B-aligned (offsets multiple of 4 floats).
// ---------------------------------------------------------------------------
__global__ __launch_bounds__(256, 3)
void attn_kernel(float* __restrict__ out) {
    extern __shared__ float sm3[];
    float* ksh = sm3;                        // 49*129 = 6321, padded to 6336
    float* vsh = sm3 + 6336;                 // 49*128 = 6272  (16B aligned)
    float* qsh = sm3 + 6336 + 6272;          // 12608: 16*128 = 2048 (16B aligned)
    float* lg  = sm3 + 6336 + 6272 + 2048;   // 14656: 16*197 = 3152
    float* am  = lg + 3152;                  // 17808: 16*49  = 784 -> end 18592
    float* osh = lg;                         // reuse lg region: 128*17 = 2176 (scalar)

    const int tid = threadIdx.x;
    const int bx = blockIdx.x, by = blockIdx.y;
    int ks_h = min(max(by - 3, 0), 25);
    int ks_w = min(max(bx - 3, 0), 25);

    // stage K, V windows (49 pixels x 128 ch)
    for (int idx = tid; idx < 6272; idx += 256) {
        int kk = idx >> 7, c = idx & 127;
        int m = kk / 7, n = kk - m * 7;
        int gp = (ks_h + m) * 32 + (ks_w + n);
        ksh[kk * 129 + c] = g_kd[gp * 128 + c];
        vsh[kk * 128 + c] = g_vd[gp * 128 + c];
    }
    // stage Q (16 queries x 128 ch)
    for (int idx = tid; idx < 2048; idx += 256) {
        int qq = idx >> 7, c = idx & 127;
        int gi = by * 4 + (qq >> 2), gj = bx * 4 + (qq & 3);
        qsh[idx] = g_qn[(gi * 128 + gj) * 128 + c];
    }
    __syncthreads();

    // phase 1: logits, 2 queries per job to halve shared loads
    for (int job = tid; job < 1568; job += 256) {
        int qp = job / 196;
        int hkk = job - qp * 196;
        int h = hkk / 49;
        int kk = hkk - h * 49;
        const float* kp = ksh + kk * 129 + h * 32;
        const float* q0 = qsh + (qp * 2) * 128 + h * 32;
        const float* q1 = q0 + 128;
        float a0 = 0.f, a1 = 0.f;
#pragma unroll
        for (int c = 0; c < 32; c++) {
            float kv = kp[c];
            a0 += q0[c] * kv;
            a1 += q1[c] * kv;
        }
        lg[(qp * 2) * 197 + hkk] = a0 * SCALE;
        lg[(qp * 2 + 1) * 197 + hkk] = a1 * SCALE;
    }
    __syncthreads();

    // phase 2: per-(q,h) softmax, pre-scaled by 1/4 for head-mean
    if (tid < 64) {
        int q = tid >> 2, h = tid & 3;
        float* base = lg + q * 197 + h * 49;
        float mx = base[0];
        for (int k = 1; k < 49; k++) mx = fmaxf(mx, base[k]);
        float s = 0.f;
        for (int k = 0; k < 49; k++) { float e = __expf(base[k] - mx); base[k] = e; s += e; }
        float inv = 0.25f / s;
        for (int k = 0; k < 49; k++) base[k] *= inv;
    }
    __syncthreads();
    // phase 2b: head-mean attention weights
    for (int job = tid; job < 784; job += 256) {
        int q = job / 49, kk = job - q * 49;
        const float* b = lg + q * 197 + kk;
        am[job] = b[0] + b[49] + b[98] + b[147];
    }
    __syncthreads();

    // phase 3: out[q][c] = sum_kk am[q][kk] * V[kk][c]; thread = (q, 8 channels)
    {
        const int q = tid >> 4;
        const int cb = (tid & 15) * 8;
        float racc[8];
#pragma unroll
        for (int j = 0; j < 8; j++) racc[j] = 0.f;
        const float* amq = am + q * 49;
        for (int kk = 0; kk < 49; kk++) {
            float a = amq[kk];
            const float4 v0 = *(const float4*)(vsh + kk * 128 + cb);
            const float4 v1 = *(const float4*)(vsh + kk * 128 + cb + 4);
            racc[0] += a * v0.x; racc[1] += a * v0.y;
            racc[2] += a * v0.z; racc[3] += a * v0.w;
            racc[4] += a * v1.x; racc[5] += a * v1.y;
            racc[6] += a * v1.z; racc[7] += a * v1.w;
        }
        // osh overlaps lg which is no longer read (am is a separate buffer)
#pragma unroll
        for (int j = 0; j < 8; j++) osh[(cb + j) * 17 + q] = racc[j];
    }
    __syncthreads();
    // final store: [c][4x4 pixel tile] as float4 rows
    for (int job = tid; job < 512; job += 256) {
        int c = job >> 2, i = job & 3;
        const float* b = osh + c * 17 + i * 4;
        float4 v;
        v.x = b[0]; v.y = b[1]; v.z = b[2]; v.w = b[3];
        *(float4*)(out + c * 16384 + (by * 4 + i) * 128 + bx * 4) = v;
    }
}

// ---------------------------------------------------------------------------
extern "C" void kernel_launch(void* const* d_in, const int* in_sizes, int n_in,
                              void* d_out, int out_size) {
    const float* q  = (const float*)d_in[0];
    const float* k  = (const float*)d_in[1];
    const float* v  = (const float*)d_in[2];
    const float* cw = (const float*)d_in[3];
    const float* nq = (const float*)d_in[4];
    const float* nk = (const float*)d_in[5];
    const float* qw = (const float*)d_in[6];
    const float* qb = (const float*)d_in[7];
    const float* kw = (const float*)d_in[8];
    const float* kb = (const float*)d_in[9];
    float* out = (float*)d_out;

    cudaFuncSetAttribute(convq_kernel, cudaFuncAttributeMaxDynamicSharedMemorySize, 84624);
    cudaFuncSetAttribute(attn_kernel, cudaFuncAttributeMaxDynamicSharedMemorySize, 74368);

    prep_kernel<<<576, 256>>>(cw, nq, nk, qw, kw);
    convq_kernel<<<dim3(16, 16), 256, 84624>>>(q, qb);
    kprep_kernel<<<64, 256, 41088>>>(k, v, kb);
    attn_kernel<<<dim3(32, 32), 256, 74368>>>(out);
}

// round 5
// speedup vs baseline: 2.0509x; 2.0475x over previous
#include <cuda_runtime.h>
#include <cuda_bf16.h>
#include <cstdint>

#define EPS   1.1920928955078125e-07f
#define SCALE 0.17677669529663687f   // 1/sqrt(32)

// ---------------------------------------------------------------------------
// scratch (static __device__ — no allocations allowed)
// ---------------------------------------------------------------------------
__device__ __align__(16) unsigned short g_cwp[36 * 9216];  // conv W bf16 [tap][ch][hi/lo] planes: [128oc][72 stride] (64 ci used)
__device__ __align__(16) unsigned short g_wqp[4 * 9216];   // qproj W bf16 [ch][hi/lo] planes
__device__ __align__(16) float g_wkt[128 * 128];           // kproj_w^T * normk_w, [c][o]
__device__ __align__(16) float g_qn[128 * 128 * 128];      // projected q, [pixel][c]
__device__ __align__(16) float g_kd[32 * 32 * 128];        // projected k (downsampled), [pixel][c]
__device__ __align__(16) float g_vd[32 * 32 * 128];        // v transposed, [pixel][c]

// ---------------------------------------------------------------------------
// helpers
// ---------------------------------------------------------------------------
__device__ __forceinline__ uint32_t smem_u32(const void* p) {
    uint32_t a;
    asm("{ .reg .u64 t; cvta.to.shared.u64 t, %1; cvt.u32.u64 %0, t; }" : "=r"(a) : "l"(p));
    return a;
}
__device__ __forceinline__ void ldsm4(uint32_t& r0, uint32_t& r1, uint32_t& r2, uint32_t& r3,
                                      uint32_t addr) {
    asm volatile("ldmatrix.sync.aligned.m8n8.x4.shared.b16 {%0,%1,%2,%3}, [%4];"
                 : "=r"(r0), "=r"(r1), "=r"(r2), "=r"(r3) : "r"(addr));
}
__device__ __forceinline__ void mma16816(float* c, const uint32_t* a, uint32_t b0, uint32_t b1) {
    asm volatile("mma.sync.aligned.m16n8k16.row.col.f32.bf16.bf16.f32 "
                 "{%0,%1,%2,%3}, {%4,%5,%6,%7}, {%8,%9}, {%0,%1,%2,%3};"
                 : "+f"(c[0]), "+f"(c[1]), "+f"(c[2]), "+f"(c[3])
                 : "r"(a[0]), "r"(a[1]), "r"(a[2]), "r"(a[3]), "r"(b0), "r"(b1));
}
__device__ __forceinline__ void split2(float v0, float v1, uint32_t& hw, uint32_t& lw) {
    __nv_bfloat16 h0 = __float2bfloat16(v0), h1 = __float2bfloat16(v1);
    float r0 = v0 - __bfloat162float(h0), r1 = v1 - __bfloat162float(h1);
    __nv_bfloat16 l0 = __float2bfloat16(r0), l1 = __float2bfloat16(r1);
    hw = (uint32_t)__bfloat16_as_ushort(h0) | ((uint32_t)__bfloat16_as_ushort(h1) << 16);
    lw = (uint32_t)__bfloat16_as_ushort(l0) | ((uint32_t)__bfloat16_as_ushort(l1) << 16);
}

// ---------------------------------------------------------------------------
// Kernel 0: weight prep — bf16 hi/lo split, [oc][ci] planes (stride 72)
// ---------------------------------------------------------------------------
__global__ void prep_kernel(const float* __restrict__ conv_w,
                            const float* __restrict__ normq,
                            const float* __restrict__ normk,
                            const float* __restrict__ qw,
                            const float* __restrict__ kw) {
    int idx = blockIdx.x * 256 + threadIdx.x;      // 576*256 = 147456 = 9*128*128
    if (idx < 147456) {
        int oc = idx & 127;
        int ci = (idx >> 7) & 127;
        int tap = idx >> 14;
        float w = conv_w[(oc * 128 + ci) * 9 + tap];
        __nv_bfloat16 h = __float2bfloat16(w);
        __nv_bfloat16 l = __float2bfloat16(w - __bfloat162float(h));
        int ch = ci >> 6, cl = ci & 63;
        size_t base = (size_t)((tap * 2 + ch) * 2) * 9216;
        g_cwp[base + oc * 72 + cl]        = __bfloat16_as_ushort(h);
        g_cwp[base + 9216 + oc * 72 + cl] = __bfloat16_as_ushort(l);
    }
    if (idx < 16384) {
        int o = idx & 127;
        int c = idx >> 7;
        g_wkt[idx] = kw[o * 128 + c] * normk[c];
        float v = qw[o * 128 + c] * normq[c];
        __nv_bfloat16 h = __float2bfloat16(v);
        __nv_bfloat16 l = __float2bfloat16(v - __bfloat162float(h));
        int ch = c >> 6, cl = c & 63;
        size_t base = (size_t)(ch * 2) * 9216;
        g_wqp[base + o * 72 + cl]        = __bfloat16_as_ushort(h);
        g_wqp[base + 9216 + o * 72 + cl] = __bfloat16_as_ushort(l);
    }
}

// ---------------------------------------------------------------------------
// Kernel 1: conv3x3 + RMSNorm + qproj via mma.sync bf16 (2-term split, 3 products)
// Grid (8,16): block = 8 rows x 16 cols of pixels (M=128) x 128 oc (N=128).
// 8 warps: warpM = wid&3 (32 rows), warpN = wid>>2 (64 cols).
// smem: patch hi/lo planes (180 px x 136 stride) | 4 weight planes | misc.
// ---------------------------------------------------------------------------
__global__ __launch_bounds__(256, 1)
void convq_mma(const float* __restrict__ qin, const float* __restrict__ qb) {
    extern __shared__ char smc[];
    const int OF_PL = 48960;               // patch lo plane (hi at 0); 180*272 B each
    const int OF_B  = 97920;               // 4 weight planes x 18432 B
    const int OF_SSQ  = 171648;            // 2*128 floats
    const int OF_RSTD = 172672;            // 128 floats
    const int OF_BIAS = 173184;            // 128 floats
    const int OF_CH = 0, OF_CL = 34816;    // conv-out planes (128*272 B), overlay patch

    const uint32_t sb = smem_u32(smc);
    const int tid = threadIdx.x;
    const int lane = tid & 31, wid = tid >> 5;
    const int warpM = wid & 3, warpN = wid >> 2;
    const int arow = lane & 15, khalf = lane >> 4;          // A lane mapping
    const int bn_off = (lane & 7) | ((lane >> 1) & 8);      // B lane mapping
    const int bk_half = (lane >> 3) & 1;

    float* sbias = (float*)(smc + OF_BIAS);
    if (tid < 128) sbias[tid] = qb[tid];

    // load patch (10x18 px, 128 ci), zero-padded, split bf16 hi/lo planes
    {
        unsigned short* ph = (unsigned short*)smc;
        unsigned short* pl = (unsigned short*)(smc + OF_PL);
        const int gy0 = blockIdx.y * 8 - 1, gx0 = blockIdx.x * 16 - 1;
        for (int idx = tid; idx < 23040; idx += 256) {
            int ci = idx / 180, pix = idx - ci * 180;
            int py = pix / 18, px = pix - py * 18;
            int gy = gy0 + py, gx = gx0 + px;
            float x = 0.f;
            if ((unsigned)gy < 128u && (unsigned)gx < 128u) x = qin[ci * 16384 + gy * 128 + gx];
            __nv_bfloat16 h = __float2bfloat16(x);
            __nv_bfloat16 l = __float2bfloat16(x - __bfloat162float(h));
            ph[pix * 136 + ci] = __bfloat16_as_ushort(h);
            pl[pix * 136 + ci] = __bfloat16_as_ushort(l);
        }
    }

    // per-thread A row components (per m16 fragment)
    int rowq[2], colq[2];
#pragma unroll
    for (int mf = 0; mf < 2; mf++) {
        int r = warpM * 32 + mf * 16 + arow;
        rowq[mf] = r >> 4;
        colq[mf] = r & 15;
    }

    float c[2][8][4];
#pragma unroll
    for (int mf = 0; mf < 2; mf++)
#pragma unroll
        for (int nf = 0; nf < 8; nf++)
#pragma unroll
            for (int j = 0; j < 4; j++) c[mf][nf][j] = 0.f;

    for (int tap = 0; tap < 9; tap++) {
        const int dy = tap / 3, dx = tap - dy * 3;
        __syncthreads();   // prior-tap reads done (also covers patch writes on tap 0)
        {
            const uint4* gB = (const uint4*)(g_cwp + (size_t)tap * 4 * 9216);
            uint4* sB = (uint4*)(smc + OF_B);
            for (int j = tid; j < 4608; j += 256) sB[j] = gB[j];
        }
        __syncthreads();

        uint32_t apix[2];
#pragma unroll
        for (int mf = 0; mf < 2; mf++)
            apix[mf] = sb + ((rowq[mf] + dy) * 18 + colq[mf] + dx) * 272;

#pragma unroll
        for (int ch = 0; ch < 2; ch++) {
            const uint32_t Bh = sb + OF_B + ch * 2 * 18432;
            const uint32_t Bl = Bh + 18432;
#pragma unroll
            for (int ks = 0; ks < 4; ks++) {
                const int acol2 = (ch * 64 + ks * 16 + khalf * 8) * 2;
                uint32_t ah[2][4], al[2][4];
                ldsm4(ah[0][0], ah[0][1], ah[0][2], ah[0][3], apix[0] + acol2);
                ldsm4(ah[1][0], ah[1][1], ah[1][2], ah[1][3], apix[1] + acol2);
                ldsm4(al[0][0], al[0][1], al[0][2], al[0][3], apix[0] + OF_PL + acol2);
                ldsm4(al[1][0], al[1][1], al[1][2], al[1][3], apix[1] + OF_PL + acol2);
                const int bofs = (warpN * 64 + bn_off) * 144 + (ks * 16 + bk_half * 8) * 2;
#pragma unroll
                for (int np = 0; np < 4; np++) {
                    uint32_t bh0, bh1, bh2, bh3, bl0, bl1, bl2, bl3;
                    ldsm4(bh0, bh1, bh2, bh3, Bh + bofs + np * 16 * 144);
                    ldsm4(bl0, bl1, bl2, bl3, Bl + bofs + np * 16 * 144);
#pragma unroll
                    for (int mf = 0; mf < 2; mf++) {
                        mma16816(c[mf][np * 2],     ah[mf], bh0, bh1);
                        mma16816(c[mf][np * 2 + 1], ah[mf], bh2, bh3);
                        mma16816(c[mf][np * 2],     ah[mf], bl0, bl1);
                        mma16816(c[mf][np * 2 + 1], ah[mf], bl2, bl3);
                        mma16816(c[mf][np * 2],     al[mf], bh0, bh1);
                        mma16816(c[mf][np * 2 + 1], al[mf], bh2, bh3);
                    }
                }
            }
        }
    }

    // ---- RMS over channels (cross-warp: two N-warps share each row) ----
    float s[2][2];
#pragma unroll
    for (int mf = 0; mf < 2; mf++) { s[mf][0] = 0.f; s[mf][1] = 0.f; }
#pragma unroll
    for (int mf = 0; mf < 2; mf++)
#pragma unroll
        for (int nf = 0; nf < 8; nf++) {
            s[mf][0] += c[mf][nf][0] * c[mf][nf][0] + c[mf][nf][1] * c[mf][nf][1];
            s[mf][1] += c[mf][nf][2] * c[mf][nf][2] + c[mf][nf][3] * c[mf][nf][3];
        }
#pragma unroll
    for (int off = 1; off <= 2; off <<= 1) {
#pragma unroll
        for (int mf = 0; mf < 2; mf++) {
            s[mf][0] += __shfl_xor_sync(0xffffffffu, s[mf][0], off);
            s[mf][1] += __shfl_xor_sync(0xffffffffu, s[mf][1], off);
        }
    }
    __syncthreads();   // everyone done reading patch/B smem
    float* ssq2 = (float*)(smc + OF_SSQ);
    if ((lane & 3) == 0) {
#pragma unroll
        for (int mf = 0; mf < 2; mf++) {
            int r = warpM * 32 + mf * 16 + (lane >> 2);
            ssq2[warpN * 128 + r]     = s[mf][0];
            ssq2[warpN * 128 + r + 8] = s[mf][1];
        }
    }
    __syncthreads();
    float* rstd = (float*)(smc + OF_RSTD);
    if (tid < 128)
        rstd[tid] = rsqrtf((ssq2[tid] + ssq2[128 + tid]) * (1.0f / 128.0f) + EPS);
    __syncthreads();

    // ---- write normalized conv output as bf16 hi/lo planes (overlay patch) ----
#pragma unroll
    for (int mf = 0; mf < 2; mf++) {
        int r0 = warpM * 32 + mf * 16 + (lane >> 2);
        int r1 = r0 + 8;
        float s0 = rstd[r0], s1 = rstd[r1];
#pragma unroll
        for (int nf = 0; nf < 8; nf++) {
            int n = warpN * 64 + nf * 8 + 2 * (lane & 3);
            uint32_t hw, lw;
            split2(c[mf][nf][0] * s0, c[mf][nf][1] * s0, hw, lw);
            *(uint32_t*)(smc + OF_CH + r0 * 272 + n * 2) = hw;
            *(uint32_t*)(smc + OF_CL + r0 * 272 + n * 2) = lw;
            split2(c[mf][nf][2] * s1, c[mf][nf][3] * s1, hw, lw);
            *(uint32_t*)(smc + OF_CH + r1 * 272 + n * 2) = hw;
            *(uint32_t*)(smc + OF_CL + r1 * 272 + n * 2) = lw;
        }
    }
    // stage qproj weight planes
    {
        const uint4* gq = (const uint4*)g_wqp;
        uint4* sB = (uint4*)(smc + OF_B);
        for (int j = tid; j < 4608; j += 256) sB[j] = gq[j];
    }
#pragma unroll
    for (int mf = 0; mf < 2; mf++)
#pragma unroll
        for (int nf = 0; nf < 8; nf++)
#pragma unroll
            for (int j = 0; j < 4; j++) c[mf][nf][j] = 0.f;
    __syncthreads();

    // ---- qproj GEMM (K=128) ----
    {
        uint32_t arowaddr[2];
#pragma unroll
        for (int mf = 0; mf < 2; mf++)
            arowaddr[mf] = sb + (warpM * 32 + mf * 16 + arow) * 272;
#pragma unroll
        for (int ch = 0; ch < 2; ch++) {
            const uint32_t Bh = sb + OF_B + ch * 2 * 18432;
            const uint32_t Bl = Bh + 18432;
#pragma unroll
            for (int ks = 0; ks < 4; ks++) {
                const int acol2 = (ch * 64 + ks * 16 + khalf * 8) * 2;
                uint32_t ah[2][4], al[2][4];
                ldsm4(ah[0][0], ah[0][1], ah[0][2], ah[0][3], arowaddr[0] + OF_CH + acol2);
                ldsm4(ah[1][0], ah[1][1], ah[1][2], ah[1][3], arowaddr[1] + OF_CH + acol2);
                ldsm4(al[0][0], al[0][1], al[0][2], al[0][3], arowaddr[0] + OF_CL + acol2);
                ldsm4(al[1][0], al[1][1], al[1][2], al[1][3], arowaddr[1] + OF_CL + acol2);
                const int bofs = (warpN * 64 + bn_off) * 144 + (ks * 16 + bk_half * 8) * 2;
#pragma unroll
                for (int np = 0; np < 4; np++) {
                    uint32_t bh0, bh1, bh2, bh3, bl0, bl1, bl2, bl3;
                    ldsm4(bh0, bh1, bh2, bh3, Bh + bofs + np * 16 * 144);
                    ldsm4(bl0, bl1, bl2, bl3, Bl + bofs + np * 16 * 144);
#pragma unroll
                    for (int mf = 0; mf < 2; mf++) {
                        mma16816(c[mf][np * 2],     ah[mf], bh0, bh1);
                        mma16816(c[mf][np * 2 + 1], ah[mf], bh2, bh3);
                        mma16816(c[mf][np * 2],     ah[mf], bl0, bl1);
                        mma16816(c[mf][np * 2 + 1], ah[mf], bl2, bl3);
                        mma16816(c[mf][np * 2],     al[mf], bh0, bh1);
                        mma16816(c[mf][np * 2 + 1], al[mf], bh2, bh3);
                    }
                }
            }
        }
    }

    // ---- bias + store to g_qn [pixel][oc] ----
#pragma unroll
    for (int mf = 0; mf < 2; mf++) {
        int r0 = warpM * 32 + mf * 16 + (lane >> 2);
#pragma unroll
        for (int half = 0; half < 2; half++) {
            int r = r0 + half * 8;
            int gy = blockIdx.y * 8 + (r >> 4);
            int gx = blockIdx.x * 16 + (r & 15);
            float* orow = g_qn + (size_t)(gy * 128 + gx) * 128;
#pragma unroll
            for (int nf = 0; nf < 8; nf++) {
                int n = warpN * 64 + nf * 8 + 2 * (lane & 3);
                float2 st;
                st.x = c[mf][nf][half * 2]     + sbias[n];
                st.y = c[mf][nf][half * 2 + 1] + sbias[n + 1];
                *(float2*)(orow + n) = st;
            }
        }
    }
}

// ---------------------------------------------------------------------------
// Kernel 2: k path (RMSNorm + kproj) on 32x32 grid, plus v transpose.
// ---------------------------------------------------------------------------
__global__ __launch_bounds__(256)
void kprep_kernel(const float* __restrict__ kin, const float* __restrict__ vin,
                  const float* __restrict__ kb) {
    extern __shared__ float sm2[];
    float* ksh  = sm2;                 // 16*129 = 2064
    float* wbuf = sm2 + 2064;          // 8192
    float* rstd = sm2 + 2064 + 8192;   // 16
    const int tid = threadIdx.x;
    const int tx = tid & 15;
    const int ty = tid >> 4;
    const int pbase = blockIdx.x * 16;

    for (int idx = tid; idx < 2048; idx += 256) {
        int c = idx >> 4, pp = idx & 15;
        ksh[pp * 129 + c] = kin[c * 1024 + pbase + pp];
    }
    __syncthreads();
    if (tid < 16) {
        float ss = 0.f;
        const float* row = ksh + tid * 129;
        for (int c = 0; c < 128; c++) { float v = row[c]; ss += v * v; }
        rstd[tid] = rsqrtf(ss * (1.0f / 128.0f) + EPS);
    }
    float pacc[8];
#pragma unroll
    for (int o = 0; o < 8; o++) pacc[o] = 0.f;
    const int rofs = ty * 129;
    for (int ch = 0; ch < 2; ch++) {
        __syncthreads();
        const float4* src = (const float4*)(g_wkt + ch * 64 * 128);
        float4* dst = (float4*)wbuf;
        for (int j = tid; j < 2048; j += 256) dst[j] = src[j];
        __syncthreads();
#pragma unroll 2
        for (int cl = 0; cl < 64; cl++) {
            float in0 = ksh[rofs + ch * 64 + cl];
            const float* wrow = wbuf + cl * 128 + tx * 8;
            float4 w0 = *(const float4*)wrow;
            float4 w1 = *(const float4*)(wrow + 4);
            pacc[0] += in0 * w0.x; pacc[1] += in0 * w0.y;
            pacc[2] += in0 * w0.z; pacc[3] += in0 * w0.w;
            pacc[4] += in0 * w1.x; pacc[5] += in0 * w1.y;
            pacc[6] += in0 * w1.z; pacc[7] += in0 * w1.w;
        }
    }
    {
        float r = rstd[ty];
        float* outp = g_kd + (pbase + ty) * 128 + tx * 8;
        float4 o0, o1;
        o0.x = pacc[0] * r + kb[tx * 8 + 0];
        o0.y = pacc[1] * r + kb[tx * 8 + 1];
        o0.z = pacc[2] * r + kb[tx * 8 + 2];
        o0.w = pacc[3] * r + kb[tx * 8 + 3];
        o1.x = pacc[4] * r + kb[tx * 8 + 4];
        o1.y = pacc[5] * r + kb[tx * 8 + 5];
        o1.z = pacc[6] * r + kb[tx * 8 + 6];
        o1.w = pacc[7] * r + kb[tx * 8 + 7];
        *(float4*)outp = o0;
        *(float4*)(outp + 4) = o1;
    }
    __syncthreads();
    for (int idx = tid; idx < 2048; idx += 256) {
        int c = idx >> 4, pp = idx & 15;
        ksh[pp * 129 + c] = vin[c * 1024 + pbase + pp];
    }
    __syncthreads();
    for (int idx = tid; idx < 2048; idx += 256) {
        int pp = idx >> 7, c = idx & 127;
        g_vd[(pbase + pp) * 128 + c] = ksh[pp * 129 + c];
    }
}

// ---------------------------------------------------------------------------
// Kernel 3: NATTEN attention (unchanged from passing R3 version)
// ---------------------------------------------------------------------------
__global__ __launch_bounds__(256, 3)
void attn_kernel(float* __restrict__ out) {
    extern __shared__ float sm3[];
    float* ksh = sm3;                        // 49*129 -> pad 6336
    float* vsh = sm3 + 6336;                 // 49*128
    float* qsh = sm3 + 6336 + 6272;          // 16*128
    float* lg  = sm3 + 6336 + 6272 + 2048;   // 16*197
    float* am  = lg + 3152;                  // 16*49
    float* osh = lg;                         // reuse

    const int tid = threadIdx.x;
    const int bx = blockIdx.x, by = blockIdx.y;
    int ks_h = min(max(by - 3, 0), 25);
    int ks_w = min(max(bx - 3, 0), 25);

    for (int idx = tid; idx < 6272; idx += 256) {
        int kk = idx >> 7, c = idx & 127;
        int m = kk / 7, n = kk - m * 7;
        int gp = (ks_h + m) * 32 + (ks_w + n);
        ksh[kk * 129 + c] = g_kd[gp * 128 + c];
        vsh[kk * 128 + c] = g_vd[gp * 128 + c];
    }
    for (int idx = tid; idx < 2048; idx += 256) {
        int qq = idx >> 7, c = idx & 127;
        int gi = by * 4 + (qq >> 2), gj = bx * 4 + (qq & 3);
        qsh[idx] = g_qn[(gi * 128 + gj) * 128 + c];
    }
    __syncthreads();

    for (int job = tid; job < 1568; job += 256) {
        int qp = job / 196;
        int hkk = job - qp * 196;
        int h = hkk / 49;
        int kk = hkk - h * 49;
        const float* kp = ksh + kk * 129 + h * 32;
        const float* q0 = qsh + (qp * 2) * 128 + h * 32;
        const float* q1 = q0 + 128;
        float a0 = 0.f, a1 = 0.f;
#pragma unroll
        for (int c = 0; c < 32; c++) {
            float kv = kp[c];
            a0 += q0[c] * kv;
            a1 += q1[c] * kv;
        }
        lg[(qp * 2) * 197 + hkk] = a0 * SCALE;
        lg[(qp * 2 + 1) * 197 + hkk] = a1 * SCALE;
    }
    __syncthreads();

    if (tid < 64) {
        int q = tid >> 2, h = tid & 3;
        float* base = lg + q * 197 + h * 49;
        float mx = base[0];
        for (int k = 1; k < 49; k++) mx = fmaxf(mx, base[k]);
        float s = 0.f;
        for (int k = 0; k < 49; k++) { float e = __expf(base[k] - mx); base[k] = e; s += e; }
        float inv = 0.25f / s;
        for (int k = 0; k < 49; k++) base[k] *= inv;
    }
    __syncthreads();
    for (int job = tid; job < 784; job += 256) {
        int q = job / 49, kk = job - q * 49;
        const float* b = lg + q * 197 + kk;
        am[job] = b[0] + b[49] + b[98] + b[147];
    }
    __syncthreads();

    {
        const int q = tid >> 4;
        const int cb = (tid & 15) * 8;
        float racc[8];
#pragma unroll
        for (int j = 0; j < 8; j++) racc[j] = 0.f;
        const float* amq = am + q * 49;
        for (int kk = 0; kk < 49; kk++) {
            float a = amq[kk];
            const float4 v0 = *(const float4*)(vsh + kk * 128 + cb);
            const float4 v1 = *(const float4*)(vsh + kk * 128 + cb + 4);
            racc[0] += a * v0.x; racc[1] += a * v0.y;
            racc[2] += a * v0.z; racc[3] += a * v0.w;
            racc[4] += a * v1.x; racc[5] += a * v1.y;
            racc[6] += a * v1.z; racc[7] += a * v1.w;
        }
#pragma unroll
        for (int j = 0; j < 8; j++) osh[(cb + j) * 17 + q] = racc[j];
    }
    __syncthreads();
    for (int job = tid; job < 512; job += 256) {
        int c = job >> 2, i = job & 3;
        const float* b = osh + c * 17 + i * 4;
        float4 v;
        v.x = b[0]; v.y = b[1]; v.z = b[2]; v.w = b[3];
        *(float4*)(out + c * 16384 + (by * 4 + i) * 128 + bx * 4) = v;
    }
}

// ---------------------------------------------------------------------------
extern "C" void kernel_launch(void* const* d_in, const int* in_sizes, int n_in,
                              void* d_out, int out_size) {
    const float* q  = (const float*)d_in[0];
    const float* k  = (const float*)d_in[1];
    const float* v  = (const float*)d_in[2];
    const float* cw = (const float*)d_in[3];
    const float* nq = (const float*)d_in[4];
    const float* nk = (const float*)d_in[5];
    const float* qw = (const float*)d_in[6];
    const float* qb = (const float*)d_in[7];
    const float* kw = (const float*)d_in[8];
    const float* kb = (const float*)d_in[9];
    float* out = (float*)d_out;

    cudaFuncSetAttribute(convq_mma, cudaFuncAttributeMaxDynamicSharedMemorySize, 173696);
    cudaFuncSetAttribute(attn_kernel, cudaFuncAttributeMaxDynamicSharedMemorySize, 74368);

    prep_kernel<<<576, 256>>>(cw, nq, nk, qw, kw);
    convq_mma<<<dim3(8, 16), 256, 173696>>>(q, qb);
    kprep_kernel<<<64, 256, 41088>>>(k, v, kb);
    attn_kernel<<<dim3(32, 32), 256, 74368>>>(out);
}

// round 7
// speedup vs baseline: 2.4329x; 1.1863x over previous
#include <cuda_runtime.h>
#include <cuda_bf16.h>
#include <cstdint>

#define EPS   1.1920928955078125e-07f
#define SCALE 0.17677669529663687f   // 1/sqrt(32)

// ---------------------------------------------------------------------------
// scratch (static __device__ — no allocations allowed)
// ---------------------------------------------------------------------------
__device__ __align__(16) unsigned short g_cwp[36 * 9216];  // conv W bf16 [tap][ch][hi/lo] planes
__device__ __align__(16) unsigned short g_wqp[4 * 9216];   // qproj W bf16 planes
__device__ __align__(16) float g_wkt[128 * 128];           // kproj_w^T * normk_w
__device__ __align__(16) float g_qn[128 * 128 * 128];      // projected q, [pixel][c]
__device__ __align__(16) float g_kd[32 * 32 * 128];        // projected k, [pixel][c]

// ---------------------------------------------------------------------------
// helpers
// ---------------------------------------------------------------------------
__device__ __forceinline__ uint32_t smem_u32(const void* p) {
    uint32_t a;
    asm("{ .reg .u64 t; cvta.to.shared.u64 t, %1; cvt.u32.u64 %0, t; }" : "=r"(a) : "l"(p));
    return a;
}
__device__ __forceinline__ void ldsm4(uint32_t& r0, uint32_t& r1, uint32_t& r2, uint32_t& r3,
                                      uint32_t addr) {
    asm volatile("ldmatrix.sync.aligned.m8n8.x4.shared.b16 {%0,%1,%2,%3}, [%4];"
                 : "=r"(r0), "=r"(r1), "=r"(r2), "=r"(r3) : "r"(addr));
}
__device__ __forceinline__ void mma16816(float* c, const uint32_t* a, uint32_t b0, uint32_t b1) {
    asm volatile("mma.sync.aligned.m16n8k16.row.col.f32.bf16.bf16.f32 "
                 "{%0,%1,%2,%3}, {%4,%5,%6,%7}, {%8,%9}, {%0,%1,%2,%3};"
                 : "+f"(c[0]), "+f"(c[1]), "+f"(c[2]), "+f"(c[3])
                 : "r"(a[0]), "r"(a[1]), "r"(a[2]), "r"(a[3]), "r"(b0), "r"(b1));
}
__device__ __forceinline__ void split2(float v0, float v1, uint32_t& hw, uint32_t& lw) {
    __nv_bfloat16 h0 = __float2bfloat16(v0), h1 = __float2bfloat16(v1);
    float r0 = v0 - __bfloat162float(h0), r1 = v1 - __bfloat162float(h1);
    __nv_bfloat16 l0 = __float2bfloat16(r0), l1 = __float2bfloat16(r1);
    hw = (uint32_t)__bfloat16_as_ushort(h0) | ((uint32_t)__bfloat16_as_ushort(h1) << 16);
    lw = (uint32_t)__bfloat16_as_ushort(l0) | ((uint32_t)__bfloat16_as_ushort(l1) << 16);
}

// ---------------------------------------------------------------------------
// Kernel 0: weight prep (unchanged from R5)
// ---------------------------------------------------------------------------
__global__ void prep_kernel(const float* __restrict__ conv_w,
                            const float* __restrict__ normq,
                            const float* __restrict__ normk,
                            const float* __restrict__ qw,
                            const float* __restrict__ kw) {
    int idx = blockIdx.x * 256 + threadIdx.x;
    if (idx < 147456) {
        int oc = idx & 127;
        int ci = (idx >> 7) & 127;
        int tap = idx >> 14;
        float w = conv_w[(oc * 128 + ci) * 9 + tap];
        __nv_bfloat16 h = __float2bfloat16(w);
        __nv_bfloat16 l = __float2bfloat16(w - __bfloat162float(h));
        int ch = ci >> 6, cl = ci & 63;
        size_t base = (size_t)((tap * 2 + ch) * 2) * 9216;
        g_cwp[base + oc * 72 + cl]        = __bfloat16_as_ushort(h);
        g_cwp[base + 9216 + oc * 72 + cl] = __bfloat16_as_ushort(l);
    }
    if (idx < 16384) {
        int o = idx & 127;
        int c = idx >> 7;
        g_wkt[idx] = kw[o * 128 + c] * normk[c];
        float v = qw[o * 128 + c] * normq[c];
        __nv_bfloat16 h = __float2bfloat16(v);
        __nv_bfloat16 l = __float2bfloat16(v - __bfloat162float(h));
        int ch = c >> 6, cl = c & 63;
        size_t base = (size_t)(ch * 2) * 9216;
        g_wqp[base + o * 72 + cl]        = __bfloat16_as_ushort(h);
        g_wqp[base + 9216 + o * 72 + cl] = __bfloat16_as_ushort(l);
    }
}

// ---------------------------------------------------------------------------
// Kernel 1: conv3x3 + RMSNorm + qproj via mma.sync (unchanged from R5, validated)
// ---------------------------------------------------------------------------
__global__ __launch_bounds__(256, 1)
void convq_mma(const float* __restrict__ qin, const float* __restrict__ qb) {
    extern __shared__ char smc[];
    const int OF_PL = 48960;
    const int OF_B  = 97920;
    const int OF_SSQ  = 171648;
    const int OF_RSTD = 172672;
    const int OF_BIAS = 173184;
    const int OF_CH = 0, OF_CL = 34816;

    const uint32_t sb = smem_u32(smc);
    const int tid = threadIdx.x;
    const int lane = tid & 31, wid = tid >> 5;
    const int warpM = wid & 3, warpN = wid >> 2;
    const int arow = lane & 15, khalf = lane >> 4;
    const int bn_off = (lane & 7) | ((lane >> 1) & 8);
    const int bk_half = (lane >> 3) & 1;

    float* sbias = (float*)(smc + OF_BIAS);
    if (tid < 128) sbias[tid] = qb[tid];

    {
        unsigned short* ph = (unsigned short*)smc;
        unsigned short* pl = (unsigned short*)(smc + OF_PL);
        const int gy0 = blockIdx.y * 8 - 1, gx0 = blockIdx.x * 16 - 1;
        for (int idx = tid; idx < 23040; idx += 256) {
            int ci = idx / 180, pix = idx - ci * 180;
            int py = pix / 18, px = pix - py * 18;
            int gy = gy0 + py, gx = gx0 + px;
            float x = 0.f;
            if ((unsigned)gy < 128u && (unsigned)gx < 128u) x = qin[ci * 16384 + gy * 128 + gx];
            __nv_bfloat16 h = __float2bfloat16(x);
            __nv_bfloat16 l = __float2bfloat16(x - __bfloat162float(h));
            ph[pix * 136 + ci] = __bfloat16_as_ushort(h);
            pl[pix * 136 + ci] = __bfloat16_as_ushort(l);
        }
    }

    int rowq[2], colq[2];
#pragma unroll
    for (int mf = 0; mf < 2; mf++) {
        int r = warpM * 32 + mf * 16 + arow;
        rowq[mf] = r >> 4;
        colq[mf] = r & 15;
    }

    float c[2][8][4];
#pragma unroll
    for (int mf = 0; mf < 2; mf++)
#pragma unroll
        for (int nf = 0; nf < 8; nf++)
#pragma unroll
            for (int j = 0; j < 4; j++) c[mf][nf][j] = 0.f;

    for (int tap = 0; tap < 9; tap++) {
        const int dy = tap / 3, dx = tap - dy * 3;
        __syncthreads();
        {
            const uint4* gB = (const uint4*)(g_cwp + (size_t)tap * 4 * 9216);
            uint4* sB = (uint4*)(smc + OF_B);
            for (int j = tid; j < 4608; j += 256) sB[j] = gB[j];
        }
        __syncthreads();

        uint32_t apix[2];
#pragma unroll
        for (int mf = 0; mf < 2; mf++)
            apix[mf] = sb + ((rowq[mf] + dy) * 18 + colq[mf] + dx) * 272;

#pragma unroll
        for (int ch = 0; ch < 2; ch++) {
            const uint32_t Bh = sb + OF_B + ch * 2 * 18432;
            const uint32_t Bl = Bh + 18432;
#pragma unroll
            for (int ks = 0; ks < 4; ks++) {
                const int acol2 = (ch * 64 + ks * 16 + khalf * 8) * 2;
                uint32_t ah[2][4], al[2][4];
                ldsm4(ah[0][0], ah[0][1], ah[0][2], ah[0][3], apix[0] + acol2);
                ldsm4(ah[1][0], ah[1][1], ah[1][2], ah[1][3], apix[1] + acol2);
                ldsm4(al[0][0], al[0][1], al[0][2], al[0][3], apix[0] + OF_PL + acol2);
                ldsm4(al[1][0], al[1][1], al[1][2], al[1][3], apix[1] + OF_PL + acol2);
                const int bofs = (warpN * 64 + bn_off) * 144 + (ks * 16 + bk_half * 8) * 2;
#pragma unroll
                for (int np = 0; np < 4; np++) {
                    uint32_t bh0, bh1, bh2, bh3, bl0, bl1, bl2, bl3;
                    ldsm4(bh0, bh1, bh2, bh3, Bh + bofs + np * 16 * 144);
                    ldsm4(bl0, bl1, bl2, bl3, Bl + bofs + np * 16 * 144);
#pragma unroll
                    for (int mf = 0; mf < 2; mf++) {
                        mma16816(c[mf][np * 2],     ah[mf], bh0, bh1);
                        mma16816(c[mf][np * 2 + 1], ah[mf], bh2, bh3);
                        mma16816(c[mf][np * 2],     ah[mf], bl0, bl1);
                        mma16816(c[mf][np * 2 + 1], ah[mf], bl2, bl3);
                        mma16816(c[mf][np * 2],     al[mf], bh0, bh1);
                        mma16816(c[mf][np * 2 + 1], al[mf], bh2, bh3);
                    }
                }
            }
        }
    }

    float s[2][2];
#pragma unroll
    for (int mf = 0; mf < 2; mf++) { s[mf][0] = 0.f; s[mf][1] = 0.f; }
#pragma unroll
    for (int mf = 0; mf < 2; mf++)
#pragma unroll
        for (int nf = 0; nf < 8; nf++) {
            s[mf][0] += c[mf][nf][0] * c[mf][nf][0] + c[mf][nf][1] * c[mf][nf][1];
            s[mf][1] += c[mf][nf][2] * c[mf][nf][2] + c[mf][nf][3] * c[mf][nf][3];
        }
#pragma unroll
    for (int off = 1; off <= 2; off <<= 1) {
#pragma unroll
        for (int mf = 0; mf < 2; mf++) {
            s[mf][0] += __shfl_xor_sync(0xffffffffu, s[mf][0], off);
            s[mf][1] += __shfl_xor_sync(0xffffffffu, s[mf][1], off);
        }
    }
    __syncthreads();
    float* ssq2 = (float*)(smc + OF_SSQ);
    if ((lane & 3) == 0) {
#pragma unroll
        for (int mf = 0; mf < 2; mf++) {
            int r = warpM * 32 + mf * 16 + (lane >> 2);
            ssq2[warpN * 128 + r]     = s[mf][0];
            ssq2[warpN * 128 + r + 8] = s[mf][1];
        }
    }
    __syncthreads();
    float* rstd = (float*)(smc + OF_RSTD);
    if (tid < 128)
        rstd[tid] = rsqrtf((ssq2[tid] + ssq2[128 + tid]) * (1.0f / 128.0f) + EPS);
    __syncthreads();

#pragma unroll
    for (int mf = 0; mf < 2; mf++) {
        int r0 = warpM * 32 + mf * 16 + (lane >> 2);
        int r1 = r0 + 8;
        float s0 = rstd[r0], s1 = rstd[r1];
#pragma unroll
        for (int nf = 0; nf < 8; nf++) {
            int n = warpN * 64 + nf * 8 + 2 * (lane & 3);
            uint32_t hw, lw;
            split2(c[mf][nf][0] * s0, c[mf][nf][1] * s0, hw, lw);
            *(uint32_t*)(smc + OF_CH + r0 * 272 + n * 2) = hw;
            *(uint32_t*)(smc + OF_CL + r0 * 272 + n * 2) = lw;
            split2(c[mf][nf][2] * s1, c[mf][nf][3] * s1, hw, lw);
            *(uint32_t*)(smc + OF_CH + r1 * 272 + n * 2) = hw;
            *(uint32_t*)(smc + OF_CL + r1 * 272 + n * 2) = lw;
        }
    }
    {
        const uint4* gq = (const uint4*)g_wqp;
        uint4* sB = (uint4*)(smc + OF_B);
        for (int j = tid; j < 4608; j += 256) sB[j] = gq[j];
    }
#pragma unroll
    for (int mf = 0; mf < 2; mf++)
#pragma unroll
        for (int nf = 0; nf < 8; nf++)
#pragma unroll
            for (int j = 0; j < 4; j++) c[mf][nf][j] = 0.f;
    __syncthreads();

    {
        uint32_t arowaddr[2];
#pragma unroll
        for (int mf = 0; mf < 2; mf++)
            arowaddr[mf] = sb + (warpM * 32 + mf * 16 + arow) * 272;
#pragma unroll
        for (int ch = 0; ch < 2; ch++) {
            const uint32_t Bh = sb + OF_B + ch * 2 * 18432;
            const uint32_t Bl = Bh + 18432;
#pragma unroll
            for (int ks = 0; ks < 4; ks++) {
                const int acol2 = (ch * 64 + ks * 16 + khalf * 8) * 2;
                uint32_t ah[2][4], al[2][4];
                ldsm4(ah[0][0], ah[0][1], ah[0][2], ah[0][3], arowaddr[0] + OF_CH + acol2);
                ldsm4(ah[1][0], ah[1][1], ah[1][2], ah[1][3], arowaddr[1] + OF_CH + acol2);
                ldsm4(al[0][0], al[0][1], al[0][2], al[0][3], arowaddr[0] + OF_CL + acol2);
                ldsm4(al[1][0], al[1][1], al[1][2], al[1][3], arowaddr[1] + OF_CL + acol2);
                const int bofs = (warpN * 64 + bn_off) * 144 + (ks * 16 + bk_half * 8) * 2;
#pragma unroll
                for (int np = 0; np < 4; np++) {
                    uint32_t bh0, bh1, bh2, bh3, bl0, bl1, bl2, bl3;
                    ldsm4(bh0, bh1, bh2, bh3, Bh + bofs + np * 16 * 144);
                    ldsm4(bl0, bl1, bl2, bl3, Bl + bofs + np * 16 * 144);
#pragma unroll
                    for (int mf = 0; mf < 2; mf++) {
                        mma16816(c[mf][np * 2],     ah[mf], bh0, bh1);
                        mma16816(c[mf][np * 2 + 1], ah[mf], bh2, bh3);
                        mma16816(c[mf][np * 2],     ah[mf], bl0, bl1);
                        mma16816(c[mf][np * 2 + 1], ah[mf], bl2, bl3);
                        mma16816(c[mf][np * 2],     al[mf], bh0, bh1);
                        mma16816(c[mf][np * 2 + 1], al[mf], bh2, bh3);
                    }
                }
            }
        }
    }

#pragma unroll
    for (int mf = 0; mf < 2; mf++) {
        int r0 = warpM * 32 + mf * 16 + (lane >> 2);
#pragma unroll
        for (int half = 0; half < 2; half++) {
            int r = r0 + half * 8;
            int gy = blockIdx.y * 8 + (r >> 4);
            int gx = blockIdx.x * 16 + (r & 15);
            float* orow = g_qn + (size_t)(gy * 128 + gx) * 128;
#pragma unroll
            for (int nf = 0; nf < 8; nf++) {
                int n = warpN * 64 + nf * 8 + 2 * (lane & 3);
                float2 st;
                st.x = c[mf][nf][half * 2]     + sbias[n];
                st.y = c[mf][nf][half * 2 + 1] + sbias[n + 1];
                *(float2*)(orow + n) = st;
            }
        }
    }
}

// ---------------------------------------------------------------------------
// Kernel 2: k path (RMSNorm + kproj) on 32x32 grid (V handling removed).
// ---------------------------------------------------------------------------
__global__ __launch_bounds__(256)
void kprep_kernel(const float* __restrict__ kin, const float* __restrict__ kb) {
    extern __shared__ float sm2[];
    float* ksh  = sm2;                 // 16*129 = 2064
    float* wbuf = sm2 + 2064;          // 8192
    float* rstd = sm2 + 2064 + 8192;   // 16
    const int tid = threadIdx.x;
    const int tx = tid & 15;
    const int ty = tid >> 4;
    const int pbase = blockIdx.x * 16;

    for (int idx = tid; idx < 2048; idx += 256) {
        int c = idx >> 4, pp = idx & 15;
        ksh[pp * 129 + c] = kin[c * 1024 + pbase + pp];
    }
    __syncthreads();
    if (tid < 16) {
        float ss = 0.f;
        const float* row = ksh + tid * 129;
        for (int c = 0; c < 128; c++) { float v = row[c]; ss += v * v; }
        rstd[tid] = rsqrtf(ss * (1.0f / 128.0f) + EPS);
    }
    float pacc[8];
#pragma unroll
    for (int o = 0; o < 8; o++) pacc[o] = 0.f;
    const int rofs = ty * 129;
    for (int ch = 0; ch < 2; ch++) {
        __syncthreads();
        const float4* src = (const float4*)(g_wkt + ch * 64 * 128);
        float4* dst = (float4*)wbuf;
        for (int j = tid; j < 2048; j += 256) dst[j] = src[j];
        __syncthreads();
#pragma unroll 2
        for (int cl = 0; cl < 64; cl++) {
            float in0 = ksh[rofs + ch * 64 + cl];
            const float* wrow = wbuf + cl * 128 + tx * 8;
            float4 w0 = *(const float4*)wrow;
            float4 w1 = *(const float4*)(wrow + 4);
            pacc[0] += in0 * w0.x; pacc[1] += in0 * w0.y;
            pacc[2] += in0 * w0.z; pacc[3] += in0 * w0.w;
            pacc[4] += in0 * w1.x; pacc[5] += in0 * w1.y;
            pacc[6] += in0 * w1.z; pacc[7] += in0 * w1.w;
        }
    }
    {
        float r = rstd[ty];
        float* outp = g_kd + (pbase + ty) * 128 + tx * 8;
        float4 o0, o1;
        o0.x = pacc[0] * r + kb[tx * 8 + 0];
        o0.y = pacc[1] * r + kb[tx * 8 + 1];
        o0.z = pacc[2] * r + kb[tx * 8 + 2];
        o0.w = pacc[3] * r + kb[tx * 8 + 3];
        o1.x = pacc[4] * r + kb[tx * 8 + 4];
        o1.y = pacc[5] * r + kb[tx * 8 + 5];
        o1.z = pacc[6] * r + kb[tx * 8 + 6];
        o1.w = pacc[7] * r + kb[tx * 8 + 7];
        *(float4*)outp = o0;
        *(float4*)(outp + 4) = o1;
    }
}

// ---------------------------------------------------------------------------
// Kernel 3: NATTEN attention via mma.sync.
// One block per 4x4 query tile. Keys: 7x7 window, klin = m*7+n, padded to 64.
// smem offsets (bytes):
//   KH 0 (64x272), KL 17408, VH 34816 (128x144), VL 53248,
//   QH 71680 (16x272), QL 76032, LG 80384 (16x224 f32), AMH 94720 (16x144), AML 97024.
// ---------------------------------------------------------------------------
__global__ __launch_bounds__(256, 2)
void attn_kernel(const float* __restrict__ vin, float* __restrict__ out) {
    extern __shared__ char sma[];
    const int OF_KH = 0, OF_KL = 17408, OF_VH = 34816, OF_VL = 53248;
    const int OF_QH = 71680, OF_QL = 76032, OF_LG = 80384, OF_AMH = 94720, OF_AML = 97024;

    const uint32_t sb = smem_u32(sma);
    float* lg = (float*)(sma + OF_LG);
    const int tid = threadIdx.x;
    const int lane = tid & 31, wid = tid >> 5;
    const int arow = lane & 15, khalf = lane >> 4;
    const int bn_off = (lane & 7) | ((lane >> 1) & 8);
    const int bk_half = (lane >> 3) & 1;

    const int bx = blockIdx.x, by = blockIdx.y;
    const int ks_h = min(max(by - 3, 0), 25);
    const int ks_w = min(max(bx - 3, 0), 25);

    // ---- stage K (projected) [kk][c] bf16 hi/lo, rows padded to 64 ----
    for (int idx = tid; idx < 4096; idx += 256) {       // 64 kk x 64 c-pairs
        int kk = idx >> 6, cp = idx & 63;
        float2 v = make_float2(0.f, 0.f);
        if (kk < 49) {
            int m = kk / 7, n = kk - m * 7;
            int gp = (ks_h + m) * 32 + ks_w + n;
            v = *(const float2*)(g_kd + gp * 128 + cp * 2);
        }
        uint32_t hw, lw;
        split2(v.x, v.y, hw, lw);
        *(uint32_t*)(sma + OF_KH + kk * 272 + cp * 4) = hw;
        *(uint32_t*)(sma + OF_KL + kk * 272 + cp * 4) = lw;
    }
    // ---- stage V (raw input, channel-major) [c][kk] bf16 hi/lo ----
    for (int idx = tid; idx < 8192; idx += 256) {       // 128 c x 64 kk
        int c = idx >> 6, kk = idx & 63;
        float x = 0.f;
        if (kk < 49) {
            int m = kk / 7, n = kk - m * 7;
            x = vin[c * 1024 + (ks_h + m) * 32 + ks_w + n];
        }
        __nv_bfloat16 h = __float2bfloat16(x);
        __nv_bfloat16 l = __float2bfloat16(x - __bfloat162float(h));
        *(unsigned short*)(sma + OF_VH + c * 144 + kk * 2) = __bfloat16_as_ushort(h);
        *(unsigned short*)(sma + OF_VL + c * 144 + kk * 2) = __bfloat16_as_ushort(l);
    }
    // ---- stage Q [q][c] bf16 hi/lo, pre-scaled by 1/sqrt(hd) ----
    for (int idx = tid; idx < 1024; idx += 256) {       // 16 q x 64 c-pairs
        int q = idx >> 6, cp = idx & 63;
        int gi = by * 4 + (q >> 2), gj = bx * 4 + (q & 3);
        float2 v = *(const float2*)(g_qn + (size_t)(gi * 128 + gj) * 128 + cp * 2);
        uint32_t hw, lw;
        split2(v.x * SCALE, v.y * SCALE, hw, lw);
        *(uint32_t*)(sma + OF_QH + q * 272 + cp * 4) = hw;
        *(uint32_t*)(sma + OF_QL + q * 272 + cp * 4) = lw;
    }
    __syncthreads();

    // ---- logits: warp = (head h, key-half nh). per warp: kk tiles of 32. ----
    {
        const int h = wid & 3, nh = wid >> 2;
        float cl4[4][4];
#pragma unroll
        for (int t = 0; t < 4; t++)
#pragma unroll
            for (int j = 0; j < 4; j++) cl4[t][j] = 0.f;

        const uint32_t qbase = sb + OF_QH + arow * 272;
#pragma unroll
        for (int ks = 0; ks < 2; ks++) {
            const int acol = (h * 32 + ks * 16 + khalf * 8) * 2;
            uint32_t ah[4], al[4];
            ldsm4(ah[0], ah[1], ah[2], ah[3], qbase + acol);
            ldsm4(al[0], al[1], al[2], al[3], qbase + (OF_QL - OF_QH) + acol);
#pragma unroll
            for (int t16 = 0; t16 < 2; t16++) {
                const uint32_t baddr = sb + OF_KH + ((nh * 2 + t16) * 16 + bn_off) * 272
                                     + (h * 32 + ks * 16 + bk_half * 8) * 2;
                uint32_t bh0, bh1, bh2, bh3, bl0, bl1, bl2, bl3;
                ldsm4(bh0, bh1, bh2, bh3, baddr);
                ldsm4(bl0, bl1, bl2, bl3, baddr + (OF_KL - OF_KH));
                mma16816(cl4[t16 * 2],     ah, bh0, bh1);
                mma16816(cl4[t16 * 2 + 1], ah, bh2, bh3);
                mma16816(cl4[t16 * 2],     ah, bl0, bl1);
                mma16816(cl4[t16 * 2 + 1], ah, bl2, bl3);
                mma16816(cl4[t16 * 2],     al, bh0, bh1);
                mma16816(cl4[t16 * 2 + 1], al, bh2, bh3);
            }
        }
        // store logits to lg[q][h*56 + kk]
        const int q0 = lane >> 2;
#pragma unroll
        for (int t8 = 0; t8 < 4; t8++) {
            int kk0 = nh * 32 + t8 * 8 + 2 * (lane & 3);
            if (kk0 < 56) {
                lg[q0 * 224 + h * 56 + kk0]           = cl4[t8][0];
                lg[q0 * 224 + h * 56 + kk0 + 1]       = cl4[t8][1];
                lg[(q0 + 8) * 224 + h * 56 + kk0]     = cl4[t8][2];
                lg[(q0 + 8) * 224 + h * 56 + kk0 + 1] = cl4[t8][3];
            }
        }
    }
    __syncthreads();

    // ---- softmax per (q, h), pre-scaled by 1/4 for head-mean ----
    if (tid < 64) {
        int q = tid >> 2, h = tid & 3;
        float* base = lg + q * 224 + h * 56;
        float mx = base[0];
        for (int k = 1; k < 49; k++) mx = fmaxf(mx, base[k]);
        float s = 0.f;
        for (int k = 0; k < 49; k++) { float e = __expf(base[k] - mx); base[k] = e; s += e; }
        float inv = 0.25f / s;
        for (int k = 0; k < 49; k++) base[k] *= inv;
    }
    __syncthreads();

    // ---- head-mean -> am bf16 hi/lo planes [q][kk pad 64] ----
    for (int idx = tid; idx < 1024; idx += 256) {
        int q = idx >> 6, kk = idx & 63;
        float a = 0.f;
        if (kk < 49) {
            const float* b = lg + q * 224 + kk;
            a = b[0] + b[56] + b[112] + b[168];
        }
        __nv_bfloat16 h = __float2bfloat16(a);
        __nv_bfloat16 l = __float2bfloat16(a - __bfloat162float(h));
        *(unsigned short*)(sma + OF_AMH + q * 144 + kk * 2) = __bfloat16_as_ushort(h);
        *(unsigned short*)(sma + OF_AML + q * 144 + kk * 2) = __bfloat16_as_ushort(l);
    }
    __syncthreads();

    // ---- AV: out[q][c] = sum_kk am[q][kk] * V[kk][c]; warp = 16 channels ----
    {
        float co[2][4];
#pragma unroll
        for (int t = 0; t < 2; t++)
#pragma unroll
            for (int j = 0; j < 4; j++) co[t][j] = 0.f;

#pragma unroll
        for (int ks = 0; ks < 4; ks++) {
            const uint32_t aaddr = sb + OF_AMH + arow * 144 + (ks * 16 + khalf * 8) * 2;
            uint32_t ah[4], al[4];
            ldsm4(ah[0], ah[1], ah[2], ah[3], aaddr);
            ldsm4(al[0], al[1], al[2], al[3], aaddr + (OF_AML - OF_AMH));
            const uint32_t baddr = sb + OF_VH + (wid * 16 + bn_off) * 144
                                 + (ks * 16 + bk_half * 8) * 2;
            uint32_t bh0, bh1, bh2, bh3, bl0, bl1, bl2, bl3;
            ldsm4(bh0, bh1, bh2, bh3, baddr);
            ldsm4(bl0, bl1, bl2, bl3, baddr + (OF_VL - OF_VH));
            mma16816(co[0], ah, bh0, bh1);
            mma16816(co[1], ah, bh2, bh3);
            mma16816(co[0], ah, bl0, bl1);
            mma16816(co[1], ah, bl2, bl3);
            mma16816(co[0], al, bh0, bh1);
            mma16816(co[1], al, bh2, bh3);
        }

        // store: C frag (q0,q0+8) x (c, c+1), out[c][pix]
        const int q0 = lane >> 2;
        const int pix0 = (by * 4 + (q0 >> 2)) * 128 + bx * 4 + (q0 & 3);
        const int q1 = q0 + 8;
        const int pix1 = (by * 4 + (q1 >> 2)) * 128 + bx * 4 + (q1 & 3);
#pragma unroll
        for (int t8 = 0; t8 < 2; t8++) {
            int cch = wid * 16 + t8 * 8 + 2 * (lane & 3);
            out[cch * 16384 + pix0]       = co[t8][0];
            out[(cch + 1) * 16384 + pix0] = co[t8][1];
            out[cch * 16384 + pix1]       = co[t8][2];
            out[(cch + 1) * 16384 + pix1] = co[t8][3];
        }
    }
}

// ---------------------------------------------------------------------------
extern "C" void kernel_launch(void* const* d_in, const int* in_sizes, int n_in,
                              void* d_out, int out_size) {
    const float* q  = (const float*)d_in[0];
    const float* k  = (const float*)d_in[1];
    const float* v  = (const float*)d_in[2];
    const float* cw = (const float*)d_in[3];
    const float* nq = (const float*)d_in[4];
    const float* nk = (const float*)d_in[5];
    const float* qw = (const float*)d_in[6];
    const float* qb = (const float*)d_in[7];
    const float* kw = (const float*)d_in[8];
    const float* kb = (const float*)d_in[9];
    float* out = (float*)d_out;

    cudaFuncSetAttribute(convq_mma, cudaFuncAttributeMaxDynamicSharedMemorySize, 173696);
    cudaFuncSetAttribute(attn_kernel, cudaFuncAttributeMaxDynamicSharedMemorySize, 99328);

    prep_kernel<<<576, 256>>>(cw, nq, nk, qw, kw);
    convq_mma<<<dim3(8, 16), 256, 173696>>>(q, qb);
    kprep_kernel<<<64, 256, 10304 * 4>>>(k, kb);
    attn_kernel<<<dim3(32, 32), 256, 99328>>>(v, out);
}